// round 9
// baseline (speedup 1.0000x reference)
#include <cuda_runtime.h>
#include <cstdint>

#define NDIM 16
#define MAXN 50048

__device__ float g_deg[MAXN];
__device__ float g_dinv[MAXN];

// ---------- small utility kernels ----------
__global__ void init_kernel(const float* __restrict__ x, float* __restrict__ out, int n) {
    int i = blockIdx.x * blockDim.x + threadIdx.x;
    int nd = n * NDIM;
    if (i < nd) out[i] = x[i];
    if (i < n) g_deg[i] = 0.f;
}

__global__ void deg_kernel(const int* __restrict__ ei, int E, int n) {
    int e = blockIdx.x * blockDim.x + threadIdx.x;
    if (e >= E) return;
    int s = ei[e], d = ei[E + e];
    if ((unsigned)s < (unsigned)n) atomicAdd(&g_deg[s], 1.f);
    if ((unsigned)d < (unsigned)n) atomicAdd(&g_deg[d], 1.f);
}

__global__ void dinv_kernel(int n) {
    int i = blockIdx.x * blockDim.x + threadIdx.x;
    if (i < n) g_dinv[i] = 1.f / sqrtf(fmaxf(g_deg[i], 1e-5f));
}

__global__ void relu_kernel(float* __restrict__ out, int nd) {
    int i = blockIdx.x * blockDim.x + threadIdx.x;
    if (i < nd) out[i] = fmaxf(out[i], 0.f);
}

// ---------- main edge kernel: TWO edges per thread, weights loaded once ----------
__global__ void __launch_bounds__(128)
edge_kernel(const float* __restrict__ x, const int* __restrict__ ei,
            const float* __restrict__ W1, const float* __restrict__ b1,
            const float* __restrict__ W2, const float* __restrict__ b2,
            float* __restrict__ out, int E, int n)
{
    // sW1[k][j] = W1[j][k]  (transposed: j contiguous -> LDS.128 over j)
    __shared__ __align__(16) float sW1[32 * 64];
    // sW2[i][j] = W2[i][j]  (j contiguous)
    __shared__ __align__(16) float sW2[16 * 64];
    __shared__ float sb1[64];
    __shared__ float sb2[16];

    for (int idx = threadIdx.x; idx < 64 * 32; idx += blockDim.x) {
        int j = idx >> 5, k = idx & 31;
        sW1[k * 64 + j] = W1[idx];
    }
    for (int idx = threadIdx.x; idx < 16 * 64; idx += blockDim.x) sW2[idx] = W2[idx];
    if (threadIdx.x < 64) sb1[threadIdx.x] = b1[threadIdx.x];
    if (threadIdx.x < 16) sb2[threadIdx.x] = b2[threadIdx.x];
    __syncthreads();

    int t = blockIdx.x * blockDim.x + threadIdx.x;
    int e0 = 2 * t;

    int  s[2], d[2];
    bool ok[2];
    float in[2][32];

    #pragma unroll
    for (int pe = 0; pe < 2; pe++) {
        int e = e0 + pe;
        bool v = (e < E);
        int ss = 0, dd = 0;
        if (v) { ss = ei[e]; dd = ei[E + e]; }
        v = v && ((unsigned)ss < (unsigned)n) && ((unsigned)dd < (unsigned)n);
        s[pe] = v ? ss : 0;
        d[pe] = v ? dd : 0;
        ok[pe] = v;
        const float4* ps = (const float4*)(x + (size_t)s[pe] * NDIM);
        const float4* pd = (const float4*)(x + (size_t)d[pe] * NDIM);
        #pragma unroll
        for (int q = 0; q < 4; q++) {
            float4 a = ps[q];
            in[pe][4 * q + 0] = a.x; in[pe][4 * q + 1] = a.y;
            in[pe][4 * q + 2] = a.z; in[pe][4 * q + 3] = a.w;
        }
        #pragma unroll
        for (int q = 0; q < 4; q++) {
            float4 a = pd[q];
            in[pe][16 + 4 * q + 0] = a.x; in[pe][16 + 4 * q + 1] = a.y;
            in[pe][16 + 4 * q + 2] = a.z; in[pe][16 + 4 * q + 3] = a.w;
        }
    }

    // v0[pe] = MLP([xs,xd]), v1[pe] = MLP([xd,xs]); every weight load feeds 4 FMAs.
    float v0[2][16], v1[2][16];
    #pragma unroll
    for (int i = 0; i < 16; i++) {
        float b = sb2[i];
        v0[0][i] = b; v0[1][i] = b; v1[0][i] = b; v1[1][i] = b;
    }

    #pragma unroll 1
    for (int jj = 0; jj < 64; jj += 8) {
        float h0[2][8], h1[2][8];
        #pragma unroll
        for (int j = 0; j < 8; j++) {
            float b = sb1[jj + j];
            h0[0][j] = b; h0[1][j] = b; h1[0][j] = b; h1[1][j] = b;
        }
        #pragma unroll
        for (int k = 0; k < 32; k++) {
            const float4* wp = (const float4*)(sW1 + k * 64 + jj);  // broadcast LDS.128 x2
            float4 wa = wp[0], wb = wp[1];
            #pragma unroll
            for (int pe = 0; pe < 2; pe++) {
                float a0 = in[pe][k];        // dir0 input
                float a1 = in[pe][k ^ 16];   // dir1 input (swapped halves)
                h0[pe][0] += wa.x * a0; h1[pe][0] += wa.x * a1;
                h0[pe][1] += wa.y * a0; h1[pe][1] += wa.y * a1;
                h0[pe][2] += wa.z * a0; h1[pe][2] += wa.z * a1;
                h0[pe][3] += wa.w * a0; h1[pe][3] += wa.w * a1;
                h0[pe][4] += wb.x * a0; h1[pe][4] += wb.x * a1;
                h0[pe][5] += wb.y * a0; h1[pe][5] += wb.y * a1;
                h0[pe][6] += wb.z * a0; h1[pe][6] += wb.z * a1;
                h0[pe][7] += wb.w * a0; h1[pe][7] += wb.w * a1;
            }
        }
        #pragma unroll
        for (int pe = 0; pe < 2; pe++)
            #pragma unroll
            for (int j = 0; j < 8; j++) {
                h0[pe][j] = fmaxf(h0[pe][j], 0.f);
                h1[pe][j] = fmaxf(h1[pe][j], 0.f);
            }
        #pragma unroll
        for (int i = 0; i < 16; i++) {
            const float4* wp = (const float4*)(sW2 + i * 64 + jj);  // broadcast LDS.128 x2
            float4 wa = wp[0], wb = wp[1];
            #pragma unroll
            for (int pe = 0; pe < 2; pe++) {
                v0[pe][i] += wa.x * h0[pe][0] + wa.y * h0[pe][1] + wa.z * h0[pe][2] + wa.w * h0[pe][3]
                           + wb.x * h0[pe][4] + wb.y * h0[pe][5] + wb.z * h0[pe][6] + wb.w * h0[pe][7];
                v1[pe][i] += wa.x * h1[pe][0] + wa.y * h1[pe][1] + wa.z * h1[pe][2] + wa.w * h1[pe][3]
                           + wb.x * h1[pe][4] + wb.y * h1[pe][5] + wb.z * h1[pe][6] + wb.w * h1[pe][7];
            }
        }
    }

    #pragma unroll
    for (int pe = 0; pe < 2; pe++) {
        if (!ok[pe]) continue;

        // normalize: u = v / max(||v||, 1e-12)
        float n0 = 0.f, n1 = 0.f;
        #pragma unroll
        for (int i = 0; i < 16; i++) { n0 += v0[pe][i] * v0[pe][i]; n1 += v1[pe][i] * v1[pe][i]; }
        float inv0 = 1.f / fmaxf(sqrtf(n0), 1e-12f);
        float inv1 = 1.f / fmaxf(sqrtf(n1), 1e-12f);
        float u0[16], u1[16];
        #pragma unroll
        for (int i = 0; i < 16; i++) { u0[i] = v0[pe][i] * inv0; u1[i] = v1[pe][i] * inv1; }
        // u0 = Householder vec of F_s, u1 = of F_d

        float coef = g_dinv[s[pe]] * g_dinv[d[pe]];

        // message to src: += coef * F_s(F_d x_d);  F u y = y - 2(u.y)u
        {
            float tv[16];
            float dd2 = 0.f;
            #pragma unroll
            for (int i = 0; i < 16; i++) dd2 += u1[i] * in[pe][16 + i];
            dd2 *= 2.f;
            #pragma unroll
            for (int i = 0; i < 16; i++) tv[i] = in[pe][16 + i] - dd2 * u1[i];
            float ds = 0.f;
            #pragma unroll
            for (int i = 0; i < 16; i++) ds += u0[i] * tv[i];
            ds *= 2.f;
            float* po = out + (size_t)s[pe] * NDIM;
            #pragma unroll
            for (int i = 0; i < 16; i++) atomicAdd(po + i, coef * (tv[i] - ds * u0[i]));
        }

        // message to dst: += coef * F_d(F_s x_s)
        {
            float tv[16];
            float ss2 = 0.f;
            #pragma unroll
            for (int i = 0; i < 16; i++) ss2 += u0[i] * in[pe][i];
            ss2 *= 2.f;
            #pragma unroll
            for (int i = 0; i < 16; i++) tv[i] = in[pe][i] - ss2 * u0[i];
            float sd = 0.f;
            #pragma unroll
            for (int i = 0; i < 16; i++) sd += u1[i] * tv[i];
            sd *= 2.f;
            float* pq = out + (size_t)d[pe] * NDIM;
            #pragma unroll
            for (int i = 0; i < 16; i++) atomicAdd(pq + i, coef * (tv[i] - sd * u1[i]));
        }
    }
}

extern "C" void kernel_launch(void* const* d_in, const int* in_sizes, int n_in,
                              void* d_out, int out_size) {
    const float* x  = (const float*)d_in[0];
    const int*   ei = (const int*)d_in[1];
    const float* W1 = (const float*)d_in[2];
    const float* b1 = (const float*)d_in[3];
    const float* W2 = (const float*)d_in[4];
    const float* b2 = (const float*)d_in[5];
    float* out = (float*)d_out;

    int n  = in_sizes[0] / NDIM;
    int E  = in_sizes[1] / 2;
    int nd = n * NDIM;

    init_kernel<<<(nd + 255) / 256, 256>>>(x, out, n);
    deg_kernel<<<(E + 255) / 256, 256>>>(ei, E, n);
    dinv_kernel<<<(n + 255) / 256, 256>>>(n);
    int nt = (E + 1) / 2;                       // two edges per thread
    edge_kernel<<<(nt + 127) / 128, 128>>>(x, ei, W1, b1, W2, b2, out, E, n);
    relu_kernel<<<(nd + 255) / 256, 256>>>(out, nd);
}

// round 10
// speedup vs baseline: 1.3116x; 1.3116x over previous
#include <cuda_runtime.h>
#include <cstdint>

#define NDIM 16
#define MAXN 50048

__device__ float g_deg[MAXN];
__device__ float g_dinv[MAXN];

// ---------- packed f32x2 helpers ----------
__device__ __forceinline__ void ffma2(uint64_t &acc, uint64_t a, uint64_t b) {
    asm("fma.rn.f32x2 %0, %1, %2, %0;" : "+l"(acc) : "l"(a), "l"(b));
}
__device__ __forceinline__ uint64_t pack2(float lo, float hi) {
    uint64_t r; asm("mov.b64 %0, {%1, %2};" : "=l"(r) : "f"(lo), "f"(hi)); return r;
}
__device__ __forceinline__ void unpack2(uint64_t v, float &lo, float &hi) {
    asm("mov.b64 {%0, %1}, %2;" : "=f"(lo), "=f"(hi) : "l"(v));
}
__device__ __forceinline__ void red_add_v4(float* p, float a, float b, float c, float d) {
    asm volatile("red.global.add.v4.f32 [%0], {%1, %2, %3, %4};"
                 :: "l"(p), "f"(a), "f"(b), "f"(c), "f"(d) : "memory");
}

// ---------- small utility kernels ----------
__global__ void init_kernel(const float* __restrict__ x, float* __restrict__ out, int n) {
    int i = blockIdx.x * blockDim.x + threadIdx.x;
    int nd = n * NDIM;
    if (i < nd) out[i] = x[i];
    if (i < n) g_deg[i] = 0.f;
}

__global__ void deg_kernel(const int* __restrict__ ei, int E, int n) {
    int e = blockIdx.x * blockDim.x + threadIdx.x;
    if (e >= E) return;
    int s = ei[e], d = ei[E + e];
    if ((unsigned)s < (unsigned)n) atomicAdd(&g_deg[s], 1.f);
    if ((unsigned)d < (unsigned)n) atomicAdd(&g_deg[d], 1.f);
}

__global__ void dinv_kernel(int n) {
    int i = blockIdx.x * blockDim.x + threadIdx.x;
    if (i < n) g_dinv[i] = 1.f / sqrtf(fmaxf(g_deg[i], 1e-5f));
}

__global__ void relu_kernel(float* __restrict__ out, int nd) {
    int i = blockIdx.x * blockDim.x + threadIdx.x;
    if (i < nd) out[i] = fmaxf(out[i], 0.f);
}

// ---------- main edge kernel: one edge/thread, f32x2 MLP, vector reductions ----------
__global__ void __launch_bounds__(128)
edge_kernel(const float* __restrict__ x, const int* __restrict__ ei,
            const float* __restrict__ W1, const float* __restrict__ b1,
            const float* __restrict__ W2, const float* __restrict__ b2,
            float* __restrict__ out, int E, int n)
{
    // sW1[k][j] = W1[j][k]  (transposed: j contiguous -> LDS.128 gives packed (j,j+1) pairs)
    __shared__ __align__(16) float sW1[32 * 64];
    // sW2[i][j] = W2[i][j]
    __shared__ __align__(16) float sW2[16 * 64];
    __shared__ float sb1[64];
    __shared__ float sb2[16];

    for (int idx = threadIdx.x; idx < 64 * 32; idx += blockDim.x) {
        int j = idx >> 5, k = idx & 31;
        sW1[k * 64 + j] = W1[idx];
    }
    for (int idx = threadIdx.x; idx < 16 * 64; idx += blockDim.x) sW2[idx] = W2[idx];
    if (threadIdx.x < 64) sb1[threadIdx.x] = b1[threadIdx.x];
    if (threadIdx.x < 16) sb2[threadIdx.x] = b2[threadIdx.x];
    __syncthreads();

    int e = blockIdx.x * blockDim.x + threadIdx.x;
    if (e >= E) return;
    int s = ei[e];
    int d = ei[E + e];
    if ((unsigned)s >= (unsigned)n || (unsigned)d >= (unsigned)n) return;

    // in[0..15] = x[src], in[16..31] = x[dst]
    float in[32];
    {
        const float4* ps = (const float4*)(x + (size_t)s * NDIM);
        const float4* pd = (const float4*)(x + (size_t)d * NDIM);
        #pragma unroll
        for (int q = 0; q < 4; q++) {
            float4 a = ps[q];
            in[4 * q + 0] = a.x; in[4 * q + 1] = a.y;
            in[4 * q + 2] = a.z; in[4 * q + 3] = a.w;
        }
        #pragma unroll
        for (int q = 0; q < 4; q++) {
            float4 a = pd[q];
            in[16 + 4 * q + 0] = a.x; in[16 + 4 * q + 1] = a.y;
            in[16 + 4 * q + 2] = a.z; in[16 + 4 * q + 3] = a.w;
        }
    }

    // vp0[i] = packed (even-j partial, odd-j partial) of v_dir0[i]; vp1 for dir1.
    uint64_t vp0[16], vp1[16];
    #pragma unroll
    for (int i = 0; i < 16; i++) { vp0[i] = 0ull; vp1[i] = 0ull; }

    #pragma unroll 1
    for (int jj = 0; jj < 64; jj += 8) {
        // hp[dir][p] = packed (h_{jj+2p}, h_{jj+2p+1})
        uint64_t hp0[4], hp1[4];
        #pragma unroll
        for (int p = 0; p < 4; p++) {
            uint64_t b = pack2(sb1[jj + 2 * p], sb1[jj + 2 * p + 1]);
            hp0[p] = b; hp1[p] = b;
        }
        #pragma unroll
        for (int k = 0; k < 32; k++) {
            ulonglong2 wa = *(const ulonglong2*)(sW1 + k * 64 + jj);      // pairs (j0,j1),(j2,j3)
            ulonglong2 wb = *(const ulonglong2*)(sW1 + k * 64 + jj + 4);  // pairs (j4,j5),(j6,j7)
            uint64_t A0 = pack2(in[k], in[k]);
            uint64_t A1 = pack2(in[k ^ 16], in[k ^ 16]);
            ffma2(hp0[0], wa.x, A0); ffma2(hp1[0], wa.x, A1);
            ffma2(hp0[1], wa.y, A0); ffma2(hp1[1], wa.y, A1);
            ffma2(hp0[2], wb.x, A0); ffma2(hp1[2], wb.x, A1);
            ffma2(hp0[3], wb.y, A0); ffma2(hp1[3], wb.y, A1);
        }
        // ReLU on packed pairs
        #pragma unroll
        for (int p = 0; p < 4; p++) {
            float l, h;
            unpack2(hp0[p], l, h);
            hp0[p] = pack2(fmaxf(l, 0.f), fmaxf(h, 0.f));
            unpack2(hp1[p], l, h);
            hp1[p] = pack2(fmaxf(l, 0.f), fmaxf(h, 0.f));
        }
        // W2 pass: pairs over j feed packed accumulators
        #pragma unroll
        for (int i = 0; i < 16; i++) {
            ulonglong2 wa = *(const ulonglong2*)(sW2 + i * 64 + jj);
            ulonglong2 wb = *(const ulonglong2*)(sW2 + i * 64 + jj + 4);
            ffma2(vp0[i], wa.x, hp0[0]); ffma2(vp1[i], wa.x, hp1[0]);
            ffma2(vp0[i], wa.y, hp0[1]); ffma2(vp1[i], wa.y, hp1[1]);
            ffma2(vp0[i], wb.x, hp0[2]); ffma2(vp1[i], wb.x, hp1[2]);
            ffma2(vp0[i], wb.y, hp0[3]); ffma2(vp1[i], wb.y, hp1[3]);
        }
    }

    // reduce pairs, add bias, normalize
    float u0[16], u1[16];
    float n0 = 0.f, n1 = 0.f;
    #pragma unroll
    for (int i = 0; i < 16; i++) {
        float l, h;
        unpack2(vp0[i], l, h);
        float v = l + h + sb2[i];
        u0[i] = v; n0 += v * v;
        unpack2(vp1[i], l, h);
        v = l + h + sb2[i];
        u1[i] = v; n1 += v * v;
    }
    float inv0 = 1.f / fmaxf(sqrtf(n0), 1e-12f);
    float inv1 = 1.f / fmaxf(sqrtf(n1), 1e-12f);
    #pragma unroll
    for (int i = 0; i < 16; i++) { u0[i] *= inv0; u1[i] *= inv1; }
    // u0 = Householder vec of F_s, u1 = of F_d

    float coef = g_dinv[s] * g_dinv[d];

    // message to src: += coef * F_s(F_d x_d);  F u y = y - 2(u.y)u
    {
        float tv[16];
        float dd = 0.f;
        #pragma unroll
        for (int i = 0; i < 16; i++) dd += u1[i] * in[16 + i];
        dd *= 2.f;
        #pragma unroll
        for (int i = 0; i < 16; i++) tv[i] = in[16 + i] - dd * u1[i];
        float ds = 0.f;
        #pragma unroll
        for (int i = 0; i < 16; i++) ds += u0[i] * tv[i];
        ds *= 2.f;
        float* po = out + (size_t)s * NDIM;
        #pragma unroll
        for (int q = 0; q < 4; q++)
            red_add_v4(po + 4 * q,
                       coef * (tv[4 * q + 0] - ds * u0[4 * q + 0]),
                       coef * (tv[4 * q + 1] - ds * u0[4 * q + 1]),
                       coef * (tv[4 * q + 2] - ds * u0[4 * q + 2]),
                       coef * (tv[4 * q + 3] - ds * u0[4 * q + 3]));
    }

    // message to dst: += coef * F_d(F_s x_s)
    {
        float tv[16];
        float ss = 0.f;
        #pragma unroll
        for (int i = 0; i < 16; i++) ss += u0[i] * in[i];
        ss *= 2.f;
        #pragma unroll
        for (int i = 0; i < 16; i++) tv[i] = in[i] - ss * u0[i];
        float sd = 0.f;
        #pragma unroll
        for (int i = 0; i < 16; i++) sd += u1[i] * tv[i];
        sd *= 2.f;
        float* pq = out + (size_t)d * NDIM;
        #pragma unroll
        for (int q = 0; q < 4; q++)
            red_add_v4(pq + 4 * q,
                       coef * (tv[4 * q + 0] - sd * u1[4 * q + 0]),
                       coef * (tv[4 * q + 1] - sd * u1[4 * q + 1]),
                       coef * (tv[4 * q + 2] - sd * u1[4 * q + 2]),
                       coef * (tv[4 * q + 3] - sd * u1[4 * q + 3]));
    }
}

extern "C" void kernel_launch(void* const* d_in, const int* in_sizes, int n_in,
                              void* d_out, int out_size) {
    const float* x  = (const float*)d_in[0];
    const int*   ei = (const int*)d_in[1];
    const float* W1 = (const float*)d_in[2];
    const float* b1 = (const float*)d_in[3];
    const float* W2 = (const float*)d_in[4];
    const float* b2 = (const float*)d_in[5];
    float* out = (float*)d_out;

    int n  = in_sizes[0] / NDIM;
    int E  = in_sizes[1] / 2;
    int nd = n * NDIM;

    init_kernel<<<(nd + 255) / 256, 256>>>(x, out, n);
    deg_kernel<<<(E + 255) / 256, 256>>>(ei, E, n);
    dinv_kernel<<<(n + 255) / 256, 256>>>(n);
    edge_kernel<<<(E + 127) / 128, 128>>>(x, ei, W1, b1, W2, b2, out, E, n);
    relu_kernel<<<(nd + 255) / 256, 256>>>(out, nd);
}